// round 3
// baseline (speedup 1.0000x reference)
#include <cuda_runtime.h>
#include <cstdint>

// ---------------- problem constants (fixed by the dataset) ----------------
#define NMAX   60000
#define VMAX   50000
#define SEQL   30
#define HD     100      // hidden / feature dim
#define G3     300      // 3 * HD
#define NSM    152      // GB300 SM count

// ---------------- device scratch (static: no runtime allocation) ----------
// g_embW layout is PERMUTED: embW[v*300 + jc*60 + g*20 + i]
//   == (emb[v] . W_ih[g*100 + jc*20 + i]) + b_ih[g*100 + jc*20 + i]
__device__ float g_embW[VMAX * G3];
__device__ float g_hn  [NMAX * HD];     // GRU final hidden
__device__ float g_xw  [NMAX * HD];     // x @ W (reused for both convs)
__device__ float g_xc1 [NMAX * HD];     // conv1 output (pre-relu)
__device__ float g_xc2 [NMAX * HD];     // conv2 output (pre-relu)
__device__ float g_x   [NMAX * 2*HD];   // relu(concat(xc1, root1))
__device__ float g_dinv[NMAX];
__device__ int   g_deg [NMAX];

// ---------------- small helpers ----------------
typedef unsigned long long u64;

__device__ __forceinline__ u64 pack2(float lo, float hi) {
    u64 r; asm("mov.b64 %0, {%1, %2};" : "=l"(r) : "f"(lo), "f"(hi)); return r;
}
__device__ __forceinline__ void unpack2(u64 v, float &lo, float &hi) {
    asm("mov.b64 {%0, %1}, %2;" : "=f"(lo), "=f"(hi) : "l"(v));
}
__device__ __forceinline__ u64 fma2(u64 a, u64 b, u64 c) {
    u64 d; asm("fma.rn.f32x2 %0, %1, %2, %3;" : "=l"(d) : "l"(a), "l"(b), "l"(c)); return d;
}
__device__ __forceinline__ float sigmf(float x) {
    return __fdividef(1.f, 1.f + __expf(-x));
}
__device__ __forceinline__ float tanh_f(float x) {
    return fmaf(2.f, __fdividef(1.f, 1.f + __expf(-2.f * x)), -1.f);
}

// ================= degree / normalization =================
__global__ void k_deg_init(int N) {
    int i = blockIdx.x * blockDim.x + threadIdx.x;
    if (i < N) g_deg[i] = 1;             // self-loop
}
__global__ void k_deg_edges(const int* __restrict__ ei, int E) {
    int e = blockIdx.x * blockDim.x + threadIdx.x;
    if (e < E) atomicAdd(&g_deg[ei[E + e]], 1);   // dst = second row
}
__global__ void k_dinv(int N) {
    int i = blockIdx.x * blockDim.x + threadIdx.x;
    if (i < N) g_dinv[i] = rsqrtf((float)g_deg[i]);
}

// ================= kernel: embW (persistent tiled GEMM) ====================
// embW[v][c'] with c' = jc*60 + g*20 + i  <->  W_ih row (g*100 + jc*20 + i)
// 320 threads: thread (v = tid&63, jc = tid>>6). 64 vocab rows per tile.
// Each thread owns 60 output columns -> 30 f32x2 accumulators.
#define EMBW_SMEM ((30000 + 6400) * 4)

__global__ __launch_bounds__(320, 1)
void k_embW(const float* __restrict__ emb, const float* __restrict__ W_ih,
            const float* __restrict__ b_ih, int V, int ntiles)
{
    extern __shared__ float sm[];
    float* sW = sm;           // [100][300] permuted: sW[k*300 + c']
    float* se = sm + 30000;   // [100][64]  se[k*64 + n] = emb[v][k]

    const int tid = threadIdx.x;
    const int n   = tid & 63;
    const int jc  = tid >> 6;

    // load W_ih transposed + permuted (once per block)
    for (int idx = tid; idx < G3 * HD; idx += 320) {
        int k = idx / G3, c = idx - k * G3;
        int jcc = c / 60, r = c - jcc * 60;
        int g = r / 20, i = r - g * 20;
        sW[idx] = W_ih[(g * HD + jcc * 20 + i) * HD + k];
    }

    for (int tile = blockIdx.x; tile < ntiles; tile += gridDim.x) {
        const int base = tile * 64;
        __syncthreads();   // protect se from previous iteration readers
        for (int idx = tid; idx < 64 * HD; idx += 320) {
            int nn = idx / HD, k = idx - nn * HD;
            int vg = min(base + nn, V - 1);
            se[k * 64 + nn] = emb[vg * HD + k];
        }
        __syncthreads();

        u64 acc[30];
        #pragma unroll
        for (int p = 0; p < 30; p++) acc[p] = 0ull;

        const float* wr0 = sW + jc * 60;
        #pragma unroll 2
        for (int k = 0; k < HD; k++) {
            float xv = se[k * 64 + n];
            u64 x2 = pack2(xv, xv);
            const float* wr = wr0 + k * G3;
            #pragma unroll
            for (int p = 0; p < 30; p++) {
                u64 wv = *(const u64*)(wr + p * 2);
                acc[p] = fma2(wv, x2, acc[p]);
            }
        }

        int v = base + n;
        if (v < V) {
            float* outp = g_embW + (long long)v * G3 + jc * 60;
            #pragma unroll
            for (int p = 0; p < 30; p++) {
                int cc = p * 2;                   // 0..58 within the 60-col slice
                int g = cc / 20, i = cc - g * 20; // i even, i+1 same gate
                int row = g * HD + jc * 20 + i;   // original W_ih row
                float lo, hi; unpack2(acc[p], lo, hi);
                float2 o; o.x = lo + b_ih[row]; o.y = hi + b_ih[row + 1];
                *(float2*)(outp + cc) = o;
            }
        }
    }
}

// ================= fused persistent GRU =================
// 64 nodes per tile, 320 threads. Thread (n = tid&63, jc = tid>>6 in 0..4)
// owns columns jc*20..jc*20+19 of ALL 3 gates: 30 f32x2 accumulators.
// embW gate inputs prefetched into registers BEFORE the GEMM k-loop.
#define GRU_SMEM ((30000 + 6400 + 300) * 4 + 64 * SEQL * 4)   // 154480 B

__global__ __launch_bounds__(320, 1)
void k_gru(const float* __restrict__ h0, const int* __restrict__ feat,
           const float* __restrict__ W_hh, const float* __restrict__ b_hh,
           int n_nodes, int ntiles)
{
    extern __shared__ float sm[];
    float* sWt  = sm;             // [100][300]  sWt[k*300+j] = W_hh[j][k]
    float* sh   = sm + 30000;     // [100][64]
    float* sb   = sm + 36400;     // [300]
    int*   stok = (int*)(sm + 36700); // [30][64]

    const int tid   = threadIdx.x;
    const int n     = tid & 63;
    const int jc    = tid >> 6;           // 0..4
    const int jbase = jc * 20;

    // W_hh transpose + bias: once per block
    for (int idx = tid; idx < G3 * HD; idx += 320) {
        int j = idx / HD, k = idx - j * HD;
        sWt[k * G3 + j] = W_hh[idx];
    }
    for (int idx = tid; idx < G3; idx += 320) sb[idx] = b_hh[idx];

    for (int tile = blockIdx.x; tile < ntiles; tile += gridDim.x) {
        const int base = tile * 64;
        __syncthreads();  // protect sh/stok from previous tile
        for (int idx = tid; idx < 64 * SEQL; idx += 320) {
            int nn = idx / SEQL, t = idx - nn * SEQL;
            int ng = min(base + nn, n_nodes - 1);
            stok[t * 64 + nn] = feat[ng * SEQL + t];
        }
        for (int idx = tid; idx < 64 * HD; idx += 320) {
            int nn = idx / HD, k = idx - nn * HD;
            int ng = min(base + nn, n_nodes - 1);
            sh[k * 64 + nn] = h0[ng * HD + k];
        }
        __syncthreads();

        for (int step = 0; step < SEQL; step++) {
            // ---- prefetch gate inputs (hidden under GEMM) ----
            int tok = stok[step * 64 + n];
            const float4* ew = (const float4*)(g_embW + (long long)tok * G3 + jc * 60);
            float4 pr[15];
            #pragma unroll
            for (int t = 0; t < 15; t++) pr[t] = __ldg(ew + t);

            // ---- GEMM: acc[g][j] = sum_k h[n][k] * W_hh[g*100+j][k] ----
            u64 ar[10], az[10], an[10];
            #pragma unroll
            for (int p = 0; p < 10; p++) { ar[p] = 0ull; az[p] = 0ull; an[p] = 0ull; }

            const float* wcol = sWt + jbase;
            #pragma unroll 2
            for (int k = 0; k < HD; k++) {
                float hk = sh[k * 64 + n];
                u64 hk2 = pack2(hk, hk);
                const float* wr = wcol + k * G3;
                #pragma unroll
                for (int p2 = 0; p2 < 5; p2++) {
                    ulonglong2 wv = *(const ulonglong2*)(wr + p2 * 4);
                    ar[2*p2]   = fma2(wv.x, hk2, ar[2*p2]);
                    ar[2*p2+1] = fma2(wv.y, hk2, ar[2*p2+1]);
                    ulonglong2 zv = *(const ulonglong2*)(wr + 100 + p2 * 4);
                    az[2*p2]   = fma2(zv.x, hk2, az[2*p2]);
                    az[2*p2+1] = fma2(zv.y, hk2, az[2*p2+1]);
                    ulonglong2 nv = *(const ulonglong2*)(wr + 200 + p2 * 4);
                    an[2*p2]   = fma2(nv.x, hk2, an[2*p2]);
                    an[2*p2+1] = fma2(nv.y, hk2, an[2*p2+1]);
                }
            }
            __syncthreads();   // all reads of sh done before gate writes

            // ---- gate phase (everything in registers) ----
            #pragma unroll
            for (int q = 0; q < 5; q++) {
                int j0 = jbase + q * 4;
                float4 er = pr[q];          // gate r, cols j0..j0+3 (permuted embW)
                float4 ez = pr[5 + q];
                float4 en = pr[10 + q];
                float4 brv = *(const float4*)(sb + j0);
                float4 bzv = *(const float4*)(sb + 100 + j0);
                float4 bnv = *(const float4*)(sb + 200 + j0);
                float gr[4], gz[4], gn[4];
                unpack2(ar[2*q], gr[0], gr[1]); unpack2(ar[2*q+1], gr[2], gr[3]);
                unpack2(az[2*q], gz[0], gz[1]); unpack2(az[2*q+1], gz[2], gz[3]);
                unpack2(an[2*q], gn[0], gn[1]); unpack2(an[2*q+1], gn[2], gn[3]);
                float er_[4] = {er.x, er.y, er.z, er.w};
                float ez_[4] = {ez.x, ez.y, ez.z, ez.w};
                float en_[4] = {en.x, en.y, en.z, en.w};
                float br_[4] = {brv.x, brv.y, brv.z, brv.w};
                float bz_[4] = {bzv.x, bzv.y, bzv.z, bzv.w};
                float bn_[4] = {bnv.x, bnv.y, bnv.z, bnv.w};
                #pragma unroll
                for (int i = 0; i < 4; i++) {
                    float ho = sh[(j0 + i) * 64 + n];
                    float r  = sigmf(er_[i] + gr[i] + br_[i]);
                    float z  = sigmf(ez_[i] + gz[i] + bz_[i]);
                    float nn = tanh_f(en_[i] + r * (gn[i] + bn_[i]));
                    sh[(j0 + i) * 64 + n] = nn + z * (ho - nn);
                }
            }
            __syncthreads();   // h fully updated before next step
        }

        // write out hn
        for (int idx = tid; idx < 64 * HD; idx += 320) {
            int nn = idx / HD, k = idx - nn * HD;
            int ng = base + nn;
            if (ng < n_nodes) g_hn[ng * HD + k] = sh[k * 64 + nn];
        }
    }
}

// ================= generic small GEMM: out[N,100] = x[N,K] @ W[K,100] ======
template<int K>
__device__ __forceinline__ void gemm_body(const float* __restrict__ x,
                                          const float* __restrict__ W,
                                          float* __restrict__ outp, int N)
{
    extern __shared__ float sg[];
    float* sxT = sg;            // [K][64]
    float* sW  = sg + K * 64;   // [K][100]
    const int tid  = threadIdx.x;
    const int base = blockIdx.x * 64;
    for (int idx = tid; idx < K * 64; idx += 256) {
        int nn = idx / K, k = idx - nn * K;
        int ng = min(base + nn, N - 1);
        sxT[k * 64 + nn] = x[ng * K + k];
    }
    for (int idx = tid; idx < K * 100; idx += 256) sW[idx] = W[idx];
    __syncthreads();

    const int n = tid & 63;
    const int q = tid >> 6;          // 0..3 -> 25 outputs each
    float acc[25];
    #pragma unroll
    for (int j = 0; j < 25; j++) acc[j] = 0.f;
    #pragma unroll 4
    for (int k = 0; k < K; k++) {
        float xk = sxT[k * 64 + n];
        const float* wr = sW + k * 100 + q * 25;
        #pragma unroll
        for (int j = 0; j < 25; j++) acc[j] = fmaf(xk, wr[j], acc[j]);
    }
    int ng = base + n;
    if (ng < N) {
        float* o = outp + ng * 100 + q * 25;
        #pragma unroll
        for (int j = 0; j < 25; j++) o[j] = acc[j];
    }
}

__global__ __launch_bounds__(256) void k_gemm1(const float* __restrict__ W1, int N) {
    gemm_body<100>(g_hn, W1, g_xw, N);
}
__global__ __launch_bounds__(256) void k_gemm2(const float* __restrict__ W2, int N) {
    gemm_body<200>(g_x, W2, g_xw, N);
}

// ================= GCN self-term init + edge aggregation ===================
__device__ __forceinline__ void init_self(const float* __restrict__ b,
                                          float* __restrict__ outp, int N)
{
    int gid = blockIdx.x * blockDim.x + threadIdx.x;
    if (gid >= N * HD) return;
    int n = gid / HD, j = gid - n * HD;
    float di = g_dinv[n];
    outp[gid] = fmaf(g_xw[gid], di * di, b[j]);
}
__global__ void k_init1(const float* __restrict__ b1, int N) { init_self(b1, g_xc1, N); }
__global__ void k_init2(const float* __restrict__ b2, int N) { init_self(b2, g_xc2, N); }

__device__ __forceinline__ void edge_body(float* __restrict__ outp,
                                          const int* __restrict__ ei, int E)
{
    int gid = blockIdx.x * blockDim.x + threadIdx.x;
    if (gid >= E * 25) return;
    int e = gid / 25;
    int c = gid - e * 25;
    int src = ei[e];
    int dst = ei[E + e];
    float coef = g_dinv[src] * g_dinv[dst];
    float4 v = *(const float4*)(g_xw + src * HD + c * 4);
    float* o = outp + dst * HD + c * 4;
    atomicAdd(o + 0, v.x * coef);
    atomicAdd(o + 1, v.y * coef);
    atomicAdd(o + 2, v.z * coef);
    atomicAdd(o + 3, v.w * coef);
}
__global__ void k_edge1(const int* __restrict__ ei, int E) { edge_body(g_xc1, ei, E); }
__global__ void k_edge2(const int* __restrict__ ei, int E) { edge_body(g_xc2, ei, E); }

// ================= concat/relu glue =================
__global__ void k_build_x(const int* __restrict__ indices, int N) {
    int gid = blockIdx.x * blockDim.x + threadIdx.x;
    if (gid >= N * 2 * HD) return;
    int n = gid / (2 * HD), j = gid - n * 2 * HD;
    float v = (j < HD) ? g_xc1[n * HD + j]
                       : g_hn[indices[n] * HD + (j - HD)];
    g_x[gid] = fmaxf(v, 0.f);
}
__global__ void k_final(const int* __restrict__ indices, float* __restrict__ out, int N) {
    int gid = blockIdx.x * blockDim.x + threadIdx.x;
    if (gid >= N * 2 * HD) return;
    int n = gid / (2 * HD), j = gid - n * 2 * HD;
    float v = (j < HD) ? fmaxf(g_xc2[n * HD + j], 0.f)
                       : g_xc1[indices[n] * HD + (j - HD)];   // root2 pre-relu
    out[gid] = v;
}

// ================= launch =================
extern "C" void kernel_launch(void* const* d_in, const int* in_sizes, int n_in,
                              void* d_out, int out_size)
{
    const int*   feat    = (const int*)  d_in[0];
    const int*   ei      = (const int*)  d_in[1];
    const int*   indices = (const int*)  d_in[2];
    const float* h0      = (const float*)d_in[3];
    const float* emb     = (const float*)d_in[4];
    const float* W_ih    = (const float*)d_in[5];
    const float* W_hh    = (const float*)d_in[6];
    const float* b_ih    = (const float*)d_in[7];
    const float* b_hh    = (const float*)d_in[8];
    const float* W1      = (const float*)d_in[9];
    const float* b1      = (const float*)d_in[10];
    const float* W2      = (const float*)d_in[11];
    const float* b2      = (const float*)d_in[12];
    float* out = (float*)d_out;

    const int N = in_sizes[0] / SEQL;     // 60000
    const int E = in_sizes[1] / 2;        // 120000
    const int V = in_sizes[4] / HD;       // 50000
    const int gru_tiles  = (N + 63) / 64;
    const int embw_tiles = (V + 63) / 64;

    cudaFuncSetAttribute(k_gru,   cudaFuncAttributeMaxDynamicSharedMemorySize, GRU_SMEM);
    cudaFuncSetAttribute(k_embW,  cudaFuncAttributeMaxDynamicSharedMemorySize, EMBW_SMEM);
    cudaFuncSetAttribute(k_gemm1, cudaFuncAttributeMaxDynamicSharedMemorySize, (100*64 + 100*100) * 4);
    cudaFuncSetAttribute(k_gemm2, cudaFuncAttributeMaxDynamicSharedMemorySize, (200*64 + 200*100) * 4);

    // launch order chosen so k_gru is launch index 3 (ncu capture slot)
    k_deg_init <<<(N + 255) / 256, 256>>>(N);                               // 0
    k_deg_edges<<<(E + 255) / 256, 256>>>(ei, E);                           // 1
    k_embW<<<NSM, 320, EMBW_SMEM>>>(emb, W_ih, b_ih, V, embw_tiles);        // 2
    k_gru <<<NSM, 320, GRU_SMEM>>>(h0, feat, W_hh, b_hh, N, gru_tiles);     // 3
    k_dinv     <<<(N + 255) / 256, 256>>>(N);                               // 4

    k_gemm1<<<(N + 63) / 64, 256, (100*64 + 100*100) * 4>>>(W1, N);         // 5
    k_init1<<<(N * HD + 255) / 256, 256>>>(b1, N);                          // 6
    k_edge1<<<(E * 25 + 255) / 256, 256>>>(ei, E);                          // 7

    k_build_x<<<(N * 2 * HD + 255) / 256, 256>>>(indices, N);               // 8

    k_gemm2<<<(N + 63) / 64, 256, (200*64 + 200*100) * 4>>>(W2, N);         // 9
    k_init2<<<(N * HD + 255) / 256, 256>>>(b2, N);                          // 10
    k_edge2<<<(E * 25 + 255) / 256, 256>>>(ei, E);                          // 11

    k_final<<<(N * 2 * HD + 255) / 256, 256>>>(indices, out, N);            // 12
}

// round 4
// speedup vs baseline: 1.2762x; 1.2762x over previous
#include <cuda_runtime.h>
#include <cstdint>

// ---------------- problem constants (fixed by the dataset) ----------------
#define NMAX   60000
#define VMAX   50000
#define SEQL   30
#define HD     100      // hidden / feature dim
#define G3     300      // 3 * HD
#define NSM    152      // GB300 SM count

// ---------------- device scratch (static: no runtime allocation) ----------
// g_embW layout is PERMUTED: embW[v*300 + jc*60 + g*20 + i]
//   == (emb[v] . W_ih[g*100 + jc*20 + i]) + b_ih[g*100 + jc*20 + i]
__device__ float g_embW[VMAX * G3];
__device__ float g_hn  [NMAX * HD];     // GRU final hidden
__device__ float g_xw  [NMAX * HD];     // x @ W (reused for both convs)
__device__ float g_xc1 [NMAX * HD];     // conv1 output (pre-relu)
__device__ float g_xc2 [NMAX * HD];     // conv2 output (pre-relu)
__device__ float g_x   [NMAX * 2*HD];   // relu(concat(xc1, root1))
__device__ float g_dinv[NMAX];
__device__ int   g_deg [NMAX];

// ---------------- small helpers ----------------
typedef unsigned long long u64;

__device__ __forceinline__ u64 pack2(float lo, float hi) {
    u64 r; asm("mov.b64 %0, {%1, %2};" : "=l"(r) : "f"(lo), "f"(hi)); return r;
}
__device__ __forceinline__ void unpack2(u64 v, float &lo, float &hi) {
    asm("mov.b64 {%0, %1}, %2;" : "=f"(lo), "=f"(hi) : "l"(v));
}
__device__ __forceinline__ u64 fma2(u64 a, u64 b, u64 c) {
    u64 d; asm("fma.rn.f32x2 %0, %1, %2, %3;" : "=l"(d) : "l"(a), "l"(b), "l"(c)); return d;
}
__device__ __forceinline__ float sigmf(float x) {
    return __fdividef(1.f, 1.f + __expf(-x));
}
__device__ __forceinline__ float tanh_f(float x) {
    return fmaf(2.f, __fdividef(1.f, 1.f + __expf(-2.f * x)), -1.f);
}

// ================= degree / normalization =================
__global__ void k_deg_init(int N) {
    int i = blockIdx.x * blockDim.x + threadIdx.x;
    if (i < N) g_deg[i] = 1;             // self-loop
}
__global__ void k_deg_edges(const int* __restrict__ ei, int E) {
    int e = blockIdx.x * blockDim.x + threadIdx.x;
    if (e < E) atomicAdd(&g_deg[ei[E + e]], 1);   // dst = second row
}
__global__ void k_dinv(int N) {
    int i = blockIdx.x * blockDim.x + threadIdx.x;
    if (i < N) g_dinv[i] = rsqrtf((float)g_deg[i]);
}

// ================= kernel: embW (persistent tiled GEMM) ====================
// embW[v][c'] with c' = jc*60 + g*20 + i  <->  W_ih row (g*100 + jc*20 + i)
// 320 threads: thread (v = tid&63, jc = tid>>6). 64 vocab rows per tile.
#define EMBW_SMEM ((30000 + 6400) * 4)

__global__ __launch_bounds__(320, 1)
void k_embW(const float* __restrict__ emb, const float* __restrict__ W_ih,
            const float* __restrict__ b_ih, int V, int ntiles)
{
    extern __shared__ float sm[];
    float* sW = sm;           // [100][300] permuted: sW[k*300 + c']
    float* se = sm + 30000;   // [100][64]  se[k*64 + n] = emb[v][k]

    const int tid = threadIdx.x;
    const int n   = tid & 63;
    const int jc  = tid >> 6;

    // load W_ih transposed + permuted (once per block)
    for (int idx = tid; idx < G3 * HD; idx += 320) {
        int k = idx / G3, c = idx - k * G3;
        int jcc = c / 60, r = c - jcc * 60;
        int g = r / 20, i = r - g * 20;
        sW[idx] = W_ih[(g * HD + jcc * 20 + i) * HD + k];
    }

    for (int tile = blockIdx.x; tile < ntiles; tile += gridDim.x) {
        const int base = tile * 64;
        __syncthreads();   // protect se from previous iteration readers
        for (int idx = tid; idx < 64 * HD; idx += 320) {
            int nn = idx / HD, k = idx - nn * HD;
            int vg = min(base + nn, V - 1);
            se[k * 64 + nn] = emb[vg * HD + k];
        }
        __syncthreads();

        u64 acc[30];
        #pragma unroll
        for (int p = 0; p < 30; p++) acc[p] = 0ull;

        const float* wr0 = sW + jc * 60;
        #pragma unroll 2
        for (int k = 0; k < HD; k++) {
            float xv = se[k * 64 + n];
            u64 x2 = pack2(xv, xv);
            const float* wr = wr0 + k * G3;
            #pragma unroll
            for (int p = 0; p < 30; p++) {
                u64 wv = *(const u64*)(wr + p * 2);
                acc[p] = fma2(wv, x2, acc[p]);
            }
        }

        int v = base + n;
        if (v < V) {
            float* outp = g_embW + (long long)v * G3 + jc * 60;
            #pragma unroll
            for (int p = 0; p < 30; p++) {
                int cc = p * 2;                   // 0..58 within the 60-col slice
                int g = cc / 20, i = cc - g * 20; // i even, i+1 same gate
                int row = g * HD + jc * 20 + i;   // original W_ih row
                float lo, hi; unpack2(acc[p], lo, hi);
                float2 o; o.x = lo + b_ih[row]; o.y = hi + b_ih[row + 1];
                *(float2*)(outp + cc) = o;
            }
        }
    }
}

// ================= fused persistent GRU =================
// 128 nodes per tile, 640 threads (20 warps, 5/SMSP for latency hiding).
// Thread (n = tid&127, jc = tid>>7 in 0..4) owns columns jc*20..jc*20+19 of
// ALL 3 gates: 30 f32x2 accumulators. Gate inputs (embW) loaded in the gate
// phase, consumed immediately (no long-lived prefetch -> low reg pressure).
#define GRU_NT   128
#define GRU_TPB  640
#define GRU_SMEM ((30000 + 100*GRU_NT + 300) * 4 + GRU_NT * SEQL * 4)  // 187760 B

__global__ __launch_bounds__(GRU_TPB, 1)
void k_gru(const float* __restrict__ h0, const int* __restrict__ feat,
           const float* __restrict__ W_hh, const float* __restrict__ b_hh,
           int n_nodes, int ntiles)
{
    extern __shared__ float sm[];
    float* sWt  = sm;                       // [100][300]  sWt[k*300+j] = W_hh[j][k]
    float* sh   = sm + 30000;               // [100][128]
    float* sb   = sm + 30000 + 100*GRU_NT;  // [300]
    int*   stok = (int*)(sb + 300);         // [30][128]

    const int tid   = threadIdx.x;
    const int n     = tid & (GRU_NT - 1);
    const int jc    = tid >> 7;           // 0..4
    const int jbase = jc * 20;

    // W_hh transpose + bias: once per block
    for (int idx = tid; idx < G3 * HD; idx += GRU_TPB) {
        int j = idx / HD, k = idx - j * HD;
        sWt[k * G3 + j] = W_hh[idx];
    }
    for (int idx = tid; idx < G3; idx += GRU_TPB) sb[idx] = b_hh[idx];

    for (int tile = blockIdx.x; tile < ntiles; tile += gridDim.x) {
        const int base = tile * GRU_NT;
        __syncthreads();  // protect sh/stok from previous tile
        for (int idx = tid; idx < GRU_NT * SEQL; idx += GRU_TPB) {
            int nn = idx / SEQL, t = idx - nn * SEQL;
            int ng = min(base + nn, n_nodes - 1);
            stok[t * GRU_NT + nn] = feat[ng * SEQL + t];
        }
        for (int idx = tid; idx < GRU_NT * HD; idx += GRU_TPB) {
            int nn = idx / HD, k = idx - nn * HD;
            int ng = min(base + nn, n_nodes - 1);
            sh[k * GRU_NT + nn] = h0[ng * HD + k];
        }
        __syncthreads();

        for (int step = 0; step < SEQL; step++) {
            // ---- GEMM: acc[g][j] = sum_k h[n][k] * W_hh[g*100+j][k] ----
            u64 ar[10], az[10], an[10];
            #pragma unroll
            for (int p = 0; p < 10; p++) { ar[p] = 0ull; az[p] = 0ull; an[p] = 0ull; }

            const float* wcol = sWt + jbase;
            #pragma unroll 2
            for (int k = 0; k < HD; k++) {
                float hk = sh[k * GRU_NT + n];
                u64 hk2 = pack2(hk, hk);
                const float* wr = wcol + k * G3;
                #pragma unroll
                for (int p2 = 0; p2 < 5; p2++) {
                    ulonglong2 wv = *(const ulonglong2*)(wr + p2 * 4);
                    ar[2*p2]   = fma2(wv.x, hk2, ar[2*p2]);
                    ar[2*p2+1] = fma2(wv.y, hk2, ar[2*p2+1]);
                    ulonglong2 zv = *(const ulonglong2*)(wr + 100 + p2 * 4);
                    az[2*p2]   = fma2(zv.x, hk2, az[2*p2]);
                    az[2*p2+1] = fma2(zv.y, hk2, az[2*p2+1]);
                    ulonglong2 nv = *(const ulonglong2*)(wr + 200 + p2 * 4);
                    an[2*p2]   = fma2(nv.x, hk2, an[2*p2]);
                    an[2*p2+1] = fma2(nv.y, hk2, an[2*p2+1]);
                }
            }
            __syncthreads();   // all reads of sh done before gate writes

            // ---- gate phase: load embW slice, apply gates, update h ----
            int tok = stok[step * GRU_NT + n];
            const float4* ew = (const float4*)(g_embW + (long long)tok * G3 + jc * 60);
            #pragma unroll
            for (int q = 0; q < 5; q++) {
                int j0 = jbase + q * 4;
                float4 er = __ldg(ew + q);          // gate r, cols j0..j0+3
                float4 ez = __ldg(ew + 5 + q);
                float4 en = __ldg(ew + 10 + q);
                float4 brv = *(const float4*)(sb + j0);
                float4 bzv = *(const float4*)(sb + 100 + j0);
                float4 bnv = *(const float4*)(sb + 200 + j0);
                float gr[4], gz[4], gn[4];
                unpack2(ar[2*q], gr[0], gr[1]); unpack2(ar[2*q+1], gr[2], gr[3]);
                unpack2(az[2*q], gz[0], gz[1]); unpack2(az[2*q+1], gz[2], gz[3]);
                unpack2(an[2*q], gn[0], gn[1]); unpack2(an[2*q+1], gn[2], gn[3]);
                float er_[4] = {er.x, er.y, er.z, er.w};
                float ez_[4] = {ez.x, ez.y, ez.z, ez.w};
                float en_[4] = {en.x, en.y, en.z, en.w};
                float br_[4] = {brv.x, brv.y, brv.z, brv.w};
                float bz_[4] = {bzv.x, bzv.y, bzv.z, bzv.w};
                float bn_[4] = {bnv.x, bnv.y, bnv.z, bnv.w};
                #pragma unroll
                for (int i = 0; i < 4; i++) {
                    float ho = sh[(j0 + i) * GRU_NT + n];
                    float r  = sigmf(er_[i] + gr[i] + br_[i]);
                    float z  = sigmf(ez_[i] + gz[i] + bz_[i]);
                    float nn = tanh_f(en_[i] + r * (gn[i] + bn_[i]));
                    sh[(j0 + i) * GRU_NT + n] = nn + z * (ho - nn);
                }
            }
            __syncthreads();   // h fully updated before next step
        }

        // write out hn
        for (int idx = tid; idx < GRU_NT * HD; idx += GRU_TPB) {
            int nn = idx / HD, k = idx - nn * HD;
            int ng = base + nn;
            if (ng < n_nodes) g_hn[ng * HD + k] = sh[k * GRU_NT + nn];
        }
    }
}

// ================= generic small GEMM: out[N,100] = x[N,K] @ W[K,100] ======
template<int K>
__device__ __forceinline__ void gemm_body(const float* __restrict__ x,
                                          const float* __restrict__ W,
                                          float* __restrict__ outp, int N)
{
    extern __shared__ float sg[];
    float* sxT = sg;            // [K][64]
    float* sW  = sg + K * 64;   // [K][100]
    const int tid  = threadIdx.x;
    const int base = blockIdx.x * 64;
    for (int idx = tid; idx < K * 64; idx += 256) {
        int nn = idx / K, k = idx - nn * K;
        int ng = min(base + nn, N - 1);
        sxT[k * 64 + nn] = x[ng * K + k];
    }
    for (int idx = tid; idx < K * 100; idx += 256) sW[idx] = W[idx];
    __syncthreads();

    const int n = tid & 63;
    const int q = tid >> 6;          // 0..3 -> 25 outputs each
    float acc[25];
    #pragma unroll
    for (int j = 0; j < 25; j++) acc[j] = 0.f;
    #pragma unroll 4
    for (int k = 0; k < K; k++) {
        float xk = sxT[k * 64 + n];
        const float* wr = sW + k * 100 + q * 25;
        #pragma unroll
        for (int j = 0; j < 25; j++) acc[j] = fmaf(xk, wr[j], acc[j]);
    }
    int ng = base + n;
    if (ng < N) {
        float* o = outp + ng * 100 + q * 25;
        #pragma unroll
        for (int j = 0; j < 25; j++) o[j] = acc[j];
    }
}

__global__ __launch_bounds__(256) void k_gemm1(const float* __restrict__ W1, int N) {
    gemm_body<100>(g_hn, W1, g_xw, N);
}
__global__ __launch_bounds__(256) void k_gemm2(const float* __restrict__ W2, int N) {
    gemm_body<200>(g_x, W2, g_xw, N);
}

// ================= GCN self-term init + edge aggregation ===================
__device__ __forceinline__ void init_self(const float* __restrict__ b,
                                          float* __restrict__ outp, int N)
{
    int gid = blockIdx.x * blockDim.x + threadIdx.x;
    if (gid >= N * HD) return;
    int n = gid / HD, j = gid - n * HD;
    float di = g_dinv[n];
    outp[gid] = fmaf(g_xw[gid], di * di, b[j]);
}
__global__ void k_init1(const float* __restrict__ b1, int N) { init_self(b1, g_xc1, N); }
__global__ void k_init2(const float* __restrict__ b2, int N) { init_self(b2, g_xc2, N); }

__device__ __forceinline__ void edge_body(float* __restrict__ outp,
                                          const int* __restrict__ ei, int E)
{
    int gid = blockIdx.x * blockDim.x + threadIdx.x;
    if (gid >= E * 25) return;
    int e = gid / 25;
    int c = gid - e * 25;
    int src = ei[e];
    int dst = ei[E + e];
    float coef = g_dinv[src] * g_dinv[dst];
    float4 v = *(const float4*)(g_xw + src * HD + c * 4);
    float* o = outp + dst * HD + c * 4;
    atomicAdd(o + 0, v.x * coef);
    atomicAdd(o + 1, v.y * coef);
    atomicAdd(o + 2, v.z * coef);
    atomicAdd(o + 3, v.w * coef);
}
__global__ void k_edge1(const int* __restrict__ ei, int E) { edge_body(g_xc1, ei, E); }
__global__ void k_edge2(const int* __restrict__ ei, int E) { edge_body(g_xc2, ei, E); }

// ================= concat/relu glue =================
__global__ void k_build_x(const int* __restrict__ indices, int N) {
    int gid = blockIdx.x * blockDim.x + threadIdx.x;
    if (gid >= N * 2 * HD) return;
    int n = gid / (2 * HD), j = gid - n * 2 * HD;
    float v = (j < HD) ? g_xc1[n * HD + j]
                       : g_hn[indices[n] * HD + (j - HD)];
    g_x[gid] = fmaxf(v, 0.f);
}
__global__ void k_final(const int* __restrict__ indices, float* __restrict__ out, int N) {
    int gid = blockIdx.x * blockDim.x + threadIdx.x;
    if (gid >= N * 2 * HD) return;
    int n = gid / (2 * HD), j = gid - n * 2 * HD;
    float v = (j < HD) ? fmaxf(g_xc2[n * HD + j], 0.f)
                       : g_xc1[indices[n] * HD + (j - HD)];   // root2 pre-relu
    out[gid] = v;
}

// ================= launch =================
extern "C" void kernel_launch(void* const* d_in, const int* in_sizes, int n_in,
                              void* d_out, int out_size)
{
    const int*   feat    = (const int*)  d_in[0];
    const int*   ei      = (const int*)  d_in[1];
    const int*   indices = (const int*)  d_in[2];
    const float* h0      = (const float*)d_in[3];
    const float* emb     = (const float*)d_in[4];
    const float* W_ih    = (const float*)d_in[5];
    const float* W_hh    = (const float*)d_in[6];
    const float* b_ih    = (const float*)d_in[7];
    const float* b_hh    = (const float*)d_in[8];
    const float* W1      = (const float*)d_in[9];
    const float* b1      = (const float*)d_in[10];
    const float* W2      = (const float*)d_in[11];
    const float* b2      = (const float*)d_in[12];
    float* out = (float*)d_out;

    const int N = in_sizes[0] / SEQL;     // 60000
    const int E = in_sizes[1] / 2;        // 120000
    const int V = in_sizes[4] / HD;       // 50000
    const int gru_tiles  = (N + GRU_NT - 1) / GRU_NT;
    const int embw_tiles = (V + 63) / 64;

    cudaFuncSetAttribute(k_gru,   cudaFuncAttributeMaxDynamicSharedMemorySize, GRU_SMEM);
    cudaFuncSetAttribute(k_embW,  cudaFuncAttributeMaxDynamicSharedMemorySize, EMBW_SMEM);
    cudaFuncSetAttribute(k_gemm1, cudaFuncAttributeMaxDynamicSharedMemorySize, (100*64 + 100*100) * 4);
    cudaFuncSetAttribute(k_gemm2, cudaFuncAttributeMaxDynamicSharedMemorySize, (200*64 + 200*100) * 4);

    // launch order chosen so k_gru is launch index 3 (ncu capture slot)
    k_deg_init <<<(N + 255) / 256, 256>>>(N);                               // 0
    k_deg_edges<<<(E + 255) / 256, 256>>>(ei, E);                           // 1
    k_embW<<<NSM, 320, EMBW_SMEM>>>(emb, W_ih, b_ih, V, embw_tiles);        // 2
    k_gru <<<NSM, GRU_TPB, GRU_SMEM>>>(h0, feat, W_hh, b_hh, N, gru_tiles); // 3
    k_dinv     <<<(N + 255) / 256, 256>>>(N);                               // 4

    k_gemm1<<<(N + 63) / 64, 256, (100*64 + 100*100) * 4>>>(W1, N);         // 5
    k_init1<<<(N * HD + 255) / 256, 256>>>(b1, N);                          // 6
    k_edge1<<<(E * 25 + 255) / 256, 256>>>(ei, E);                          // 7

    k_build_x<<<(N * 2 * HD + 255) / 256, 256>>>(indices, N);               // 8

    k_gemm2<<<(N + 63) / 64, 256, (200*64 + 200*100) * 4>>>(W2, N);         // 9
    k_init2<<<(N * HD + 255) / 256, 256>>>(b2, N);                          // 10
    k_edge2<<<(E * 25 + 255) / 256, 256>>>(ei, E);                          // 11

    k_final<<<(N * 2 * HD + 255) / 256, 256>>>(indices, out, N);            // 12
}

// round 5
// speedup vs baseline: 2.1245x; 1.6647x over previous
#include <cuda_runtime.h>
#include <cstdint>

// ---------------- problem constants (fixed by the dataset) ----------------
#define NMAX   60000
#define VMAX   50000
#define SEQL   30
#define HD     100      // hidden / feature dim
#define G3     300      // 3 * HD
#define NSM    152      // GB300 SM count

// ---------------- device scratch (static: no runtime allocation) ----------
// g_embW PLAIN layout: embW[v*300 + c] = emb[v].W_ih[c] + b_ih[c], c = g*100+j
__device__ float g_embW[VMAX * G3];
__device__ float g_hn  [NMAX * HD];     // GRU final hidden
__device__ float g_xw  [NMAX * HD];     // x @ W (reused for both convs)
__device__ float g_xc1 [NMAX * HD];     // conv1 output (pre-relu)
__device__ float g_xc2 [NMAX * HD];     // conv2 output (pre-relu)
__device__ float g_x   [NMAX * 2*HD];   // relu(concat(xc1, root1))
__device__ float g_dinv[NMAX];
__device__ int   g_deg [NMAX];

// ---------------- small helpers ----------------
typedef unsigned long long u64;

__device__ __forceinline__ u64 pack2(float lo, float hi) {
    u64 r; asm("mov.b64 %0, {%1, %2};" : "=l"(r) : "f"(lo), "f"(hi)); return r;
}
__device__ __forceinline__ void unpack2(u64 v, float &lo, float &hi) {
    asm("mov.b64 {%0, %1}, %2;" : "=f"(lo), "=f"(hi) : "l"(v));
}
__device__ __forceinline__ u64 fma2(u64 a, u64 b, u64 c) {
    u64 d; asm("fma.rn.f32x2 %0, %1, %2, %3;" : "=l"(d) : "l"(a), "l"(b), "l"(c)); return d;
}
__device__ __forceinline__ float sigmf(float x) {
    return __fdividef(1.f, 1.f + __expf(-x));
}
__device__ __forceinline__ float tanh_f(float x) {
    return fmaf(2.f, __fdividef(1.f, 1.f + __expf(-2.f * x)), -1.f);
}

// ================= degree / normalization =================
__global__ void k_deg_init(int N) {
    int i = blockIdx.x * blockDim.x + threadIdx.x;
    if (i < N) g_deg[i] = 1;             // self-loop
}
__global__ void k_deg_edges(const int* __restrict__ ei, int E) {
    int e = blockIdx.x * blockDim.x + threadIdx.x;
    if (e < E) atomicAdd(&g_deg[ei[E + e]], 1);   // dst = second row
}
__global__ void k_dinv(int N) {
    int i = blockIdx.x * blockDim.x + threadIdx.x;
    if (i < N) g_dinv[i] = rsqrtf((float)g_deg[i]);
}

// ================= kernel: embW (persistent tiled GEMM, plain layout) ======
// thread (n = tid&63, jc = tid>>6) computes cols [jc*60, jc*60+60) for vocab
// row base+n. sW[k*300+c] = W_ih[c*100+k].
#define EMBW_SMEM ((30000 + 6400) * 4)

__global__ __launch_bounds__(320, 1)
void k_embW(const float* __restrict__ emb, const float* __restrict__ W_ih,
            const float* __restrict__ b_ih, int V, int ntiles)
{
    extern __shared__ float sm[];
    float* sW = sm;           // [100][300]  sW[k*300+c] = W_ih[c][k]
    float* se = sm + 30000;   // [100][64]

    const int tid = threadIdx.x;
    const int n   = tid & 63;
    const int jc  = tid >> 6;

    for (int idx = tid; idx < G3 * HD; idx += 320) {
        int c = idx / HD, k = idx - c * HD;
        sW[k * G3 + c] = W_ih[idx];
    }

    for (int tile = blockIdx.x; tile < ntiles; tile += gridDim.x) {
        const int base = tile * 64;
        __syncthreads();   // protect se from previous iteration readers
        for (int idx = tid; idx < 64 * HD; idx += 320) {
            int nn = idx / HD, k = idx - nn * HD;
            int vg = min(base + nn, V - 1);
            se[k * 64 + nn] = emb[vg * HD + k];
        }
        __syncthreads();

        u64 acc[30];
        #pragma unroll
        for (int p = 0; p < 30; p++) acc[p] = 0ull;

        const float* wr0 = sW + jc * 60;
        #pragma unroll 2
        for (int k = 0; k < HD; k++) {
            float xv = se[k * 64 + n];
            u64 x2 = pack2(xv, xv);
            const float* wr = wr0 + k * G3;
            #pragma unroll
            for (int p = 0; p < 30; p++) {
                u64 wv = *(const u64*)(wr + p * 2);
                acc[p] = fma2(wv, x2, acc[p]);
            }
        }

        int v = base + n;
        if (v < V) {
            float* outp = g_embW + (long long)v * G3 + jc * 60;
            const float* bp = b_ih + jc * 60;
            #pragma unroll
            for (int p = 0; p < 30; p++) {
                float lo, hi; unpack2(acc[p], lo, hi);
                float2 o; o.x = lo + bp[p*2]; o.y = hi + bp[p*2 + 1];
                *(float2*)(outp + p*2) = o;
            }
        }
    }
}

// ================= fused persistent GRU (warp-owns-8-nodes) =================
// 384 threads = 12 warps. Each warp independently processes groups of 8 nodes.
// Lane l owns j-columns {2l,2l+1} (set0) and {2l+64,2l+65} (set1, valid l<18)
// of ALL 3 gates. W reads are coalesced LDS.64; h reads are cheap broadcasts.
// sh is warp-private -> NO block barriers in the recurrence.
#define GRU_TPB   384
#define GRU_WARPS 12
#define GRU_SMEM  ((30000 + 300 + GRU_WARPS*800) * 4 + GRU_WARPS*240*4)  // 171120 B

__global__ __launch_bounds__(GRU_TPB, 1)
void k_gru(const float* __restrict__ h0, const int* __restrict__ feat,
           const float* __restrict__ W_hh, const float* __restrict__ b_hh,
           int n_nodes, int n_groups)
{
    extern __shared__ float sm[];
    float* sWt  = sm;              // [100][300]  sWt[k*300+j] = W_hh[j][k]
    float* sb   = sm + 30000;      // [300]
    float* shb  = sm + 30300;      // [12][8][100]  per-warp h
    int*   stkb = (int*)(sm + 30300 + GRU_WARPS*800);  // [12][8][30]

    const int tid  = threadIdx.x;
    const int wid  = tid >> 5;
    const int lane = tid & 31;

    for (int idx = tid; idx < G3 * HD; idx += GRU_TPB) {
        int j = idx / HD, k = idx - j * HD;
        sWt[k * G3 + j] = W_hh[idx];
    }
    for (int idx = tid; idx < G3; idx += GRU_TPB) sb[idx] = b_hh[idx];
    __syncthreads();

    float* sh   = shb + wid * 800;      // sh[n*100 + k]
    int*   stok = stkb + wid * 240;     // stok[n*30 + t]

    const int  c0 = 2 * lane;                 // cols c0, c0+1 (always valid)
    const bool v1 = (2 * lane + 65) < HD;     // lane <= 17
    const int  c1 = v1 ? (2 * lane + 64) : 96;

    for (int g = blockIdx.x * GRU_WARPS + wid; g < n_groups;
         g += gridDim.x * GRU_WARPS) {
        const int base = g * 8;

        for (int idx = lane; idx < 800; idx += 32) {
            int n = idx / 100, k = idx - n * 100;
            int ng = min(base + n, n_nodes - 1);
            sh[idx] = h0[ng * HD + k];
        }
        for (int idx = lane; idx < 240; idx += 32) {
            int n = idx / 30, t = idx - n * 30;
            int ng = min(base + n, n_nodes - 1);
            stok[idx] = feat[ng * SEQL + t];
        }
        __syncwarp();

        for (int step = 0; step < SEQL; step++) {
            // ---- GEMM: 48 f32x2 accumulators (6 col-pairs x 8 nodes) ----
            u64 a0r[8], a0z[8], a0n[8], a1r[8], a1z[8], a1n[8];
            #pragma unroll
            for (int n = 0; n < 8; n++) {
                a0r[n] = a0z[n] = a0n[n] = 0ull;
                a1r[n] = a1z[n] = a1n[n] = 0ull;
            }

            #pragma unroll 2
            for (int k = 0; k < HD; k++) {
                const float* wk = sWt + k * G3;
                u64 w0r = *(const u64*)(wk + c0);
                u64 w0z = *(const u64*)(wk + 100 + c0);
                u64 w0n = *(const u64*)(wk + 200 + c0);
                u64 w1r = *(const u64*)(wk + c1);
                u64 w1z = *(const u64*)(wk + 100 + c1);
                u64 w1n = *(const u64*)(wk + 200 + c1);
                #pragma unroll
                for (int n = 0; n < 8; n++) {
                    float hv = sh[n * 100 + k];       // broadcast (1 wavefront)
                    u64 h2 = pack2(hv, hv);
                    a0r[n] = fma2(w0r, h2, a0r[n]);
                    a0z[n] = fma2(w0z, h2, a0z[n]);
                    a0n[n] = fma2(w0n, h2, a0n[n]);
                    a1r[n] = fma2(w1r, h2, a1r[n]);
                    a1z[n] = fma2(w1z, h2, a1z[n]);
                    a1n[n] = fma2(w1n, h2, a1n[n]);
                }
            }
            __syncwarp();   // all lanes done reading sh before gate writes

            // ---- gate phase (thread-local, exact math) ----
            float2 br0 = *(const float2*)(sb + c0);
            float2 bz0 = *(const float2*)(sb + 100 + c0);
            float2 bn0 = *(const float2*)(sb + 200 + c0);
            float2 br1 = *(const float2*)(sb + c1);
            float2 bz1 = *(const float2*)(sb + 100 + c1);
            float2 bn1 = *(const float2*)(sb + 200 + c1);

            #pragma unroll
            for (int n = 0; n < 8; n++) {
                int tok = stok[n * 30 + step];
                const float* ew = g_embW + (long long)tok * G3;
                {   // set 0
                    float2 er = *(const float2*)(ew + c0);
                    float2 ez = *(const float2*)(ew + 100 + c0);
                    float2 en = *(const float2*)(ew + 200 + c0);
                    float2 ho = *(const float2*)(sh + n * 100 + c0);
                    float gr0, gr1, gz0, gz1, gn0, gn1;
                    unpack2(a0r[n], gr0, gr1);
                    unpack2(a0z[n], gz0, gz1);
                    unpack2(a0n[n], gn0, gn1);
                    float r0 = sigmf(er.x + gr0 + br0.x);
                    float r1 = sigmf(er.y + gr1 + br0.y);
                    float z0 = sigmf(ez.x + gz0 + bz0.x);
                    float z1 = sigmf(ez.y + gz1 + bz0.y);
                    float nn0 = tanh_f(en.x + r0 * (gn0 + bn0.x));
                    float nn1 = tanh_f(en.y + r1 * (gn1 + bn0.y));
                    float2 o;
                    o.x = nn0 + z0 * (ho.x - nn0);
                    o.y = nn1 + z1 * (ho.y - nn1);
                    *(float2*)(sh + n * 100 + c0) = o;
                }
                if (v1) {   // set 1
                    float2 er = *(const float2*)(ew + c1);
                    float2 ez = *(const float2*)(ew + 100 + c1);
                    float2 en = *(const float2*)(ew + 200 + c1);
                    float2 ho = *(const float2*)(sh + n * 100 + c1);
                    float gr0, gr1, gz0, gz1, gn0, gn1;
                    unpack2(a1r[n], gr0, gr1);
                    unpack2(a1z[n], gz0, gz1);
                    unpack2(a1n[n], gn0, gn1);
                    float r0 = sigmf(er.x + gr0 + br1.x);
                    float r1 = sigmf(er.y + gr1 + br1.y);
                    float z0 = sigmf(ez.x + gz0 + bz1.x);
                    float z1 = sigmf(ez.y + gz1 + bz1.y);
                    float nn0 = tanh_f(en.x + r0 * (gn0 + bn1.x));
                    float nn1 = tanh_f(en.y + r1 * (gn1 + bn1.y));
                    float2 o;
                    o.x = nn0 + z0 * (ho.x - nn0);
                    o.y = nn1 + z1 * (ho.y - nn1);
                    *(float2*)(sh + n * 100 + c1) = o;
                }
            }
            __syncwarp();   // writes visible before next step's GEMM reads
        }

        // ---- store hn ----
        for (int idx = lane; idx < 800; idx += 32) {
            int n = idx / 100;
            int ng = base + n;
            if (ng < n_nodes) g_hn[ng * HD + (idx - n * 100)] = sh[idx];
        }
        __syncwarp();   // done with sh before next group overwrites it
    }
}

// ================= generic small GEMM: out[N,100] = x[N,K] @ W[K,100] ======
template<int K>
__device__ __forceinline__ void gemm_body(const float* __restrict__ x,
                                          const float* __restrict__ W,
                                          float* __restrict__ outp, int N)
{
    extern __shared__ float sg[];
    float* sxT = sg;            // [K][64]
    float* sW  = sg + K * 64;   // [K][100]
    const int tid  = threadIdx.x;
    const int base = blockIdx.x * 64;
    for (int idx = tid; idx < K * 64; idx += 256) {
        int nn = idx / K, k = idx - nn * K;
        int ng = min(base + nn, N - 1);
        sxT[k * 64 + nn] = x[ng * K + k];
    }
    for (int idx = tid; idx < K * 100; idx += 256) sW[idx] = W[idx];
    __syncthreads();

    const int n = tid & 63;
    const int q = tid >> 6;          // 0..3 -> 25 outputs each
    float acc[25];
    #pragma unroll
    for (int j = 0; j < 25; j++) acc[j] = 0.f;
    #pragma unroll 4
    for (int k = 0; k < K; k++) {
        float xk = sxT[k * 64 + n];
        const float* wr = sW + k * 100 + q * 25;
        #pragma unroll
        for (int j = 0; j < 25; j++) acc[j] = fmaf(xk, wr[j], acc[j]);
    }
    int ng = base + n;
    if (ng < N) {
        float* o = outp + ng * 100 + q * 25;
        #pragma unroll
        for (int j = 0; j < 25; j++) o[j] = acc[j];
    }
}

__global__ __launch_bounds__(256) void k_gemm1(const float* __restrict__ W1, int N) {
    gemm_body<100>(g_hn, W1, g_xw, N);
}
__global__ __launch_bounds__(256) void k_gemm2(const float* __restrict__ W2, int N) {
    gemm_body<200>(g_x, W2, g_xw, N);
}

// ================= GCN self-term init + edge aggregation ===================
__device__ __forceinline__ void init_self(const float* __restrict__ b,
                                          float* __restrict__ outp, int N)
{
    int gid = blockIdx.x * blockDim.x + threadIdx.x;
    if (gid >= N * HD) return;
    int n = gid / HD, j = gid - n * HD;
    float di = g_dinv[n];
    outp[gid] = fmaf(g_xw[gid], di * di, b[j]);
}
__global__ void k_init1(const float* __restrict__ b1, int N) { init_self(b1, g_xc1, N); }
__global__ void k_init2(const float* __restrict__ b2, int N) { init_self(b2, g_xc2, N); }

__device__ __forceinline__ void edge_body(float* __restrict__ outp,
                                          const int* __restrict__ ei, int E)
{
    int gid = blockIdx.x * blockDim.x + threadIdx.x;
    if (gid >= E * 25) return;
    int e = gid / 25;
    int c = gid - e * 25;
    int src = ei[e];
    int dst = ei[E + e];
    float coef = g_dinv[src] * g_dinv[dst];
    float4 v = *(const float4*)(g_xw + src * HD + c * 4);
    float* o = outp + dst * HD + c * 4;
    atomicAdd(o + 0, v.x * coef);
    atomicAdd(o + 1, v.y * coef);
    atomicAdd(o + 2, v.z * coef);
    atomicAdd(o + 3, v.w * coef);
}
__global__ void k_edge1(const int* __restrict__ ei, int E) { edge_body(g_xc1, ei, E); }
__global__ void k_edge2(const int* __restrict__ ei, int E) { edge_body(g_xc2, ei, E); }

// ================= concat/relu glue =================
__global__ void k_build_x(const int* __restrict__ indices, int N) {
    int gid = blockIdx.x * blockDim.x + threadIdx.x;
    if (gid >= N * 2 * HD) return;
    int n = gid / (2 * HD), j = gid - n * 2 * HD;
    float v = (j < HD) ? g_xc1[n * HD + j]
                       : g_hn[indices[n] * HD + (j - HD)];
    g_x[gid] = fmaxf(v, 0.f);
}
__global__ void k_final(const int* __restrict__ indices, float* __restrict__ out, int N) {
    int gid = blockIdx.x * blockDim.x + threadIdx.x;
    if (gid >= N * 2 * HD) return;
    int n = gid / (2 * HD), j = gid - n * 2 * HD;
    float v = (j < HD) ? fmaxf(g_xc2[n * HD + j], 0.f)
                       : g_xc1[indices[n] * HD + (j - HD)];   // root2 pre-relu
    out[gid] = v;
}

// ================= launch =================
extern "C" void kernel_launch(void* const* d_in, const int* in_sizes, int n_in,
                              void* d_out, int out_size)
{
    const int*   feat    = (const int*)  d_in[0];
    const int*   ei      = (const int*)  d_in[1];
    const int*   indices = (const int*)  d_in[2];
    const float* h0      = (const float*)d_in[3];
    const float* emb     = (const float*)d_in[4];
    const float* W_ih    = (const float*)d_in[5];
    const float* W_hh    = (const float*)d_in[6];
    const float* b_ih    = (const float*)d_in[7];
    const float* b_hh    = (const float*)d_in[8];
    const float* W1      = (const float*)d_in[9];
    const float* b1      = (const float*)d_in[10];
    const float* W2      = (const float*)d_in[11];
    const float* b2      = (const float*)d_in[12];
    float* out = (float*)d_out;

    const int N = in_sizes[0] / SEQL;     // 60000
    const int E = in_sizes[1] / 2;        // 120000
    const int V = in_sizes[4] / HD;       // 50000
    const int n_groups   = (N + 7) / 8;   // 8 nodes per warp-group
    const int embw_tiles = (V + 63) / 64;

    cudaFuncSetAttribute(k_gru,   cudaFuncAttributeMaxDynamicSharedMemorySize, GRU_SMEM);
    cudaFuncSetAttribute(k_embW,  cudaFuncAttributeMaxDynamicSharedMemorySize, EMBW_SMEM);
    cudaFuncSetAttribute(k_gemm1, cudaFuncAttributeMaxDynamicSharedMemorySize, (100*64 + 100*100) * 4);
    cudaFuncSetAttribute(k_gemm2, cudaFuncAttributeMaxDynamicSharedMemorySize, (200*64 + 200*100) * 4);

    // launch order chosen so k_gru is launch index 3 (ncu capture slot)
    k_deg_init <<<(N + 255) / 256, 256>>>(N);                               // 0
    k_deg_edges<<<(E + 255) / 256, 256>>>(ei, E);                           // 1
    k_embW<<<NSM, 320, EMBW_SMEM>>>(emb, W_ih, b_ih, V, embw_tiles);        // 2
    k_gru <<<NSM, GRU_TPB, GRU_SMEM>>>(h0, feat, W_hh, b_hh, N, n_groups);  // 3
    k_dinv     <<<(N + 255) / 256, 256>>>(N);                               // 4

    k_gemm1<<<(N + 63) / 64, 256, (100*64 + 100*100) * 4>>>(W1, N);         // 5
    k_init1<<<(N * HD + 255) / 256, 256>>>(b1, N);                          // 6
    k_edge1<<<(E * 25 + 255) / 256, 256>>>(ei, E);                          // 7

    k_build_x<<<(N * 2 * HD + 255) / 256, 256>>>(indices, N);               // 8

    k_gemm2<<<(N + 63) / 64, 256, (200*64 + 200*100) * 4>>>(W2, N);         // 9
    k_init2<<<(N * HD + 255) / 256, 256>>>(b2, N);                          // 10
    k_edge2<<<(E * 25 + 255) / 256, 256>>>(ei, E);                          // 11

    k_final<<<(N * 2 * HD + 255) / 256, 256>>>(indices, out, N);            // 12
}